// round 1
// baseline (speedup 1.0000x reference)
#include <cuda_runtime.h>

#define BATCH 16
#define NSEQ  8192
#define DIM   128
#define LOGN  13
#define PAIRS_PER_BATCH (NSEQ / 2)          // 4096
#define TOTAL_PAIRS     (BATCH * PAIRS_PER_BATCH) // 65536
#define ROWS  64                              // pairs per block
#define SCALE 0.17677669529663688f            // 32^-0.5

// Scratch for M_s = scale * Wq[s] @ Wk[s]^T  (13 x 128 x 128 floats)
__device__ float g_M[LOGN * DIM * DIM];

// ---------------------------------------------------------------------------
// Precompute M. grid (13, 8), 256 threads. Wk transposed through padded smem
// so both the transpose stores and the inner-product loads are conflict-free.
// ---------------------------------------------------------------------------
__global__ void precompute_M_kernel(const float* __restrict__ w) {
    extern __shared__ float sm[];
    float* wkT  = sm;                 // [128][129] padded transpose of Wk
    float* wq16 = sm + DIM * 129;     // [16][128] tile of Wq rows

    const int s    = blockIdx.x;
    const int dblk = blockIdx.y * 16;
    const float* Wq = w + (size_t)(2 * s) * DIM * DIM;
    const float* Wk = Wq + DIM * DIM;

    for (int i = threadIdx.x; i < DIM * DIM; i += 256) {
        int e = i >> 7, t = i & 127;
        wkT[t * 129 + e] = Wk[i];     // coalesced read, conflict-free write
    }
    for (int i = threadIdx.x; i < 16 * DIM; i += 256) {
        wq16[i] = Wq[(size_t)dblk * DIM + i];
    }
    __syncthreads();

    const int e  = threadIdx.x & 127;
    const int dd = threadIdx.x >> 7;
    #pragma unroll
    for (int k = 0; k < 8; k++) {
        int dl = dd * 8 + k;
        float acc = 0.0f;
        #pragma unroll 8
        for (int t = 0; t < DIM; t++)
            acc += wq16[dl * DIM + t] * wkT[t * 129 + e];
        g_M[((size_t)s * DIM + (dblk + dl)) * DIM + e] = acc * SCALE;
    }
}

// ---------------------------------------------------------------------------
// f32x2 helpers (FFMA2 is PTX-only; ptxas won't auto-fuse from C++)
// ---------------------------------------------------------------------------
__device__ __forceinline__ unsigned long long dup2(float v) {
    unsigned long long r;
    asm("mov.b64 %0, {%1, %1};" : "=l"(r) : "f"(v));
    return r;
}
__device__ __forceinline__ void fma2(unsigned long long& d,
                                     unsigned long long a,
                                     unsigned long long b) {
    asm("fma.rn.f32x2 %0, %1, %2, %0;" : "+l"(d) : "l"(a), "l"(b));
}
__device__ __forceinline__ float2 unpack2(unsigned long long v) {
    float2 r;
    asm("mov.b64 {%0, %1}, %2;" : "=f"(r.x), "=f"(r.y) : "l"(v));
    return r;
}

// ---------------------------------------------------------------------------
// One butterfly stage.
// Block: 256 threads (8 warps), 64 pairs. Warp w owns pairs w*8 .. w*8+7.
// SMEM: M (64KB) + x_a rows stored row-pair-interleaved as float2 (32KB).
//
// GEMM inner loop per d: one LDS.128 of M (4 e's per lane, conflict-free),
// 4 dup movs, 4 broadcast LDS.64 of (x_r0[d], x_r1[d]) pairs (N=1, 1 cyc),
// 16 FFMA2 -> fma pipe is the binding resource, smem feed is ~balanced.
// ---------------------------------------------------------------------------
__global__ __launch_bounds__(256, 2)
void stage_kernel(const float* __restrict__ x,
                  const float* __restrict__ vin,
                  float* __restrict__ vout,
                  int sshift) {
    extern __shared__ float smem[];
    float*  Msh  = smem;                       // 16384 floats
    float2* xash = (float2*)(smem + DIM * DIM); // [32 row-pairs][128 d]

    const int tid  = threadIdx.x;
    const int lane = tid & 31;
    const int wid  = tid >> 5;
    const int stride = 1 << sshift;
    const float* Mg = g_M + (size_t)sshift * DIM * DIM;

    // Cooperative M load (coalesced float4)
    {
        const float4* Mg4  = (const float4*)Mg;
        float4*       Msh4 = (float4*)Msh;
        #pragma unroll
        for (int i = 0; i < 16; i++)
            Msh4[tid + i * 256] = Mg4[tid + i * 256];
    }

    // Pair indices + stage x_a rows interleaved by row-pair
    int aidx[8], bidx[8];
    #pragma unroll
    for (int i = 0; i < 8; i++) {
        int p     = blockIdx.x * ROWS + wid * 8 + i;
        int batch = p >> 12;                    // / 4096
        int r     = p & (PAIRS_PER_BATCH - 1);
        int g     = r >> sshift;
        int t     = r & (stride - 1);
        int a     = (batch << 13) + (g << (sshift + 1)) + t;
        aidx[i] = a;
        bidx[i] = a + stride;

        float4 v = ((const float4*)(x + (size_t)a * DIM))[lane];
        int rp   = (wid * 8 + i) >> 1;
        int comp = i & 1;
        float* dst = (float*)(xash + rp * DIM);
        dst[(4 * lane + 0) * 2 + comp] = v.x;
        dst[(4 * lane + 1) * 2 + comp] = v.y;
        dst[(4 * lane + 2) * 2 + comp] = v.z;
        dst[(4 * lane + 3) * 2 + comp] = v.w;
    }
    __syncthreads();

    // y[8 rows][e = 4*lane .. 4*lane+3] accumulated as f32x2 over row pairs
    unsigned long long acc[4][4];
    #pragma unroll
    for (int rp = 0; rp < 4; rp++)
        #pragma unroll
        for (int e = 0; e < 4; e++) acc[rp][e] = 0ULL;

    const float4* Msh4 = (const float4*)Msh;
    const unsigned long long* xp =
        (const unsigned long long*)(xash + (size_t)wid * 4 * DIM);

    #pragma unroll 8
    for (int d = 0; d < DIM; d++) {
        float4 m = Msh4[d * 32 + lane];
        unsigned long long m0 = dup2(m.x), m1 = dup2(m.y);
        unsigned long long m2 = dup2(m.z), m3 = dup2(m.w);
        #pragma unroll
        for (int rp = 0; rp < 4; rp++) {
            unsigned long long x2 = xp[rp * DIM + d]; // broadcast LDS.64
            fma2(acc[rp][0], x2, m0);
            fma2(acc[rp][1], x2, m1);
            fma2(acc[rp][2], x2, m2);
            fma2(acc[rp][3], x2, m3);
        }
    }

    // Dots, 2-way softmax, butterfly mix (in place on vout; each pair is
    // touched by exactly one warp, which reads both rows before writing).
    #pragma unroll
    for (int i = 0; i < 8; i++) {
        const int rp   = i >> 1;
        const int comp = i & 1;
        float2 f0 = unpack2(acc[rp][0]);
        float2 f1 = unpack2(acc[rp][1]);
        float2 f2 = unpack2(acc[rp][2]);
        float2 f3 = unpack2(acc[rp][3]);
        float y0 = comp ? f0.y : f0.x;
        float y1 = comp ? f1.y : f1.x;
        float y2 = comp ? f2.y : f2.x;
        float y3 = comp ? f3.y : f3.x;

        const int a = aidx[i], b = bidx[i];
        float4 xav = ((const float4*)(x + (size_t)a * DIM))[lane];
        float4 xbv = ((const float4*)(x + (size_t)b * DIM))[lane];
        float saa = y0 * xav.x + y1 * xav.y + y2 * xav.z + y3 * xav.w;
        float sab = y0 * xbv.x + y1 * xbv.y + y2 * xbv.z + y3 * xbv.w;
        #pragma unroll
        for (int off = 16; off; off >>= 1) {
            saa += __shfl_xor_sync(0xffffffffu, saa, off);
            sab += __shfl_xor_sync(0xffffffffu, sab, off);
        }

        float w0 = 1.0f / (1.0f + __expf(sab - saa));
        float w1 = 1.0f - w0;

        float4 va = ((const float4*)(vin + (size_t)a * DIM))[lane];
        float4 vb = ((const float4*)(vin + (size_t)b * DIM))[lane];
        float4 oa, ob;
        oa.x = w0 * va.x + w1 * vb.x;  ob.x = w1 * va.x + w0 * vb.x;
        oa.y = w0 * va.y + w1 * vb.y;  ob.y = w1 * va.y + w0 * vb.y;
        oa.z = w0 * va.z + w1 * vb.z;  ob.z = w1 * va.z + w0 * vb.z;
        oa.w = w0 * va.w + w1 * vb.w;  ob.w = w1 * va.w + w0 * vb.w;
        ((float4*)(vout + (size_t)a * DIM))[lane] = oa;
        ((float4*)(vout + (size_t)b * DIM))[lane] = ob;
    }
}

// ---------------------------------------------------------------------------
extern "C" void kernel_launch(void* const* d_in, const int* in_sizes, int n_in,
                              void* d_out, int out_size) {
    const float* x = (const float*)d_in[0];          // (16, 8192, 128) f32
    const float* w = (const float*)d_in[1];          // (16, 2, 128, 128) f32
    float* out = (float*)d_out;                       // (16, 8192, 128) f32

    const int smem_pre   = (DIM * 129 + 16 * DIM) * 4;      // 74240
    const int smem_stage = (DIM * DIM) * 4 + 32 * DIM * 8;  // 98304
    cudaFuncSetAttribute(precompute_M_kernel,
                         cudaFuncAttributeMaxDynamicSharedMemorySize, smem_pre);
    cudaFuncSetAttribute(stage_kernel,
                         cudaFuncAttributeMaxDynamicSharedMemorySize, smem_stage);

    precompute_M_kernel<<<dim3(LOGN, 8), 256, smem_pre>>>(w);

    const float* vin = x;  // stage 0 reads v from x; afterwards in-place in out
    for (int s = 0; s < LOGN; s++) {
        stage_kernel<<<TOTAL_PAIRS / ROWS, 256, smem_stage>>>(x, vin, out, s);
        vin = out;
    }
}

// round 3
// speedup vs baseline: 1.4951x; 1.4951x over previous
#include <cuda_runtime.h>
#include <cstdint>

#define DIM 128
#define LOGN 13
#define THREADS 256
#define SCALE 0.17677669529663688f   // 32^-0.5

// ---- dynamic smem byte offsets ----
// Xs : 128 x 132 f32      (x tile, row stride 132 words -> conflict-friendly)
// Msp: 64 x 136 float2    (M pairs: [kc][e] = {M[d][e], M[d+4][e]}, d=(kc>>2)*8+(kc&3))
// V  : 128 x 132 f32      (running value buffer)
// SS : 4 x 64 f32         (dot partials: ssA[2][64], scA[2][64])
#define SMO_X   0
#define SMO_M   67584
#define SMO_V   137216
#define SMO_SS  204800
#define SMEM_TOTAL 205824

// M in pair-interleaved layout: g_Mi[s][kc][e].x = M[d][e], .y = M[d+4][e]
__device__ __align__(16) float2 g_Mi[LOGN * 64 * DIM];

// ============================ helpers ============================
__device__ __forceinline__ uint32_t smem_u32(const void* p) {
    uint32_t a;
    asm("{ .reg .u64 t; cvta.to.shared.u64 t, %1; cvt.u32.u64 %0, t; }" : "=r"(a) : "l"(p));
    return a;
}
__device__ __forceinline__ void cpasync16(uint32_t dst, const void* src) {
    asm volatile("cp.async.cg.shared.global [%0], [%1], 16;" :: "r"(dst), "l"(src));
}
#define CPASYNC_COMMIT asm volatile("cp.async.commit_group;" ::: "memory")
#define CPASYNC_WAIT0  asm volatile("cp.async.wait_group 0;" ::: "memory")

__device__ __forceinline__ void mma_tf32(float* cd,
                                         uint32_t a0, uint32_t a1, uint32_t a2, uint32_t a3,
                                         uint32_t b0, uint32_t b1) {
    asm volatile("mma.sync.aligned.m16n8k8.row.col.f32.tf32.tf32.f32 "
                 "{%0,%1,%2,%3}, {%4,%5,%6,%7}, {%8,%9}, {%0,%1,%2,%3};"
                 : "+f"(cd[0]), "+f"(cd[1]), "+f"(cd[2]), "+f"(cd[3])
                 : "r"(a0), "r"(a1), "r"(a2), "r"(a3), "r"(b0), "r"(b1));
}

// insert a 0 bit at position ls (a-row index -> actual row)
__device__ __forceinline__ int insert0(int i, int ls) {
    return ((i >> ls) << (ls + 1)) | (i & ((1 << ls) - 1));
}
// remove bit ls (actual row -> a-row index of its pair)
__device__ __forceinline__ int compress(int r, int ls) {
    return ((r >> (ls + 1)) << ls) | (r & ((1 << ls) - 1));
}

// ============================ precompute M (pair-interleaved) ============================
// M[d][e] = SCALE * sum_t Wq[d][t] * Wk[e][t]
__global__ void precompute_M_kernel(const float* __restrict__ w) {
    extern __shared__ float sm[];
    float* wkT  = sm;                 // [128][129] Wk transposed (padded)
    float* wq16 = sm + DIM * 129;     // 16 rows of Wq

    const int s    = blockIdx.x;
    const int dblk = blockIdx.y * 16;
    const float* Wq = w + (size_t)(2 * s) * DIM * DIM;
    const float* Wk = Wq + DIM * DIM;

    for (int i = threadIdx.x; i < DIM * DIM; i += 256) {
        int e = i >> 7, t = i & 127;
        wkT[t * 129 + e] = Wk[i];
    }
    for (int i = threadIdx.x; i < 16 * DIM; i += 256)
        wq16[i] = Wq[(size_t)dblk * DIM + i];
    __syncthreads();

    const int e  = threadIdx.x & 127;
    const int dd = threadIdx.x >> 7;          // 0..1 -> rows dblk+dd*8 .. +7
    float acc[8];
    #pragma unroll
    for (int k = 0; k < 8; k++) {
        float a = 0.0f;
        #pragma unroll 8
        for (int t = 0; t < DIM; t++)
            a += wq16[(dd * 8 + k) * DIM + t] * wkT[t * 129 + e];
        acc[k] = a * SCALE;
    }
    // rows d = dblk + dd*8 + k ; pair (k, k+4) -> kc = (dblk/8 + dd)*4 + k
    #pragma unroll
    for (int k = 0; k < 4; k++) {
        int kc = ((dblk >> 3) + dd) * 4 + k;
        g_Mi[((size_t)s * 64 + kc) * DIM + e] = make_float2(acc[k], acc[k + 4]);
    }
}

// ============================ fused butterfly ============================
// mode 0: rows = blk*128 + rr                       (stages 0..6, strides 1..64)
// mode 1: rows = batch*8192 + t0 + 64*(rr>>6) + 128*(rr&63)  (stages 7..12)
__device__ __forceinline__ int grow_of(int mode, int blk, int rr) {
    if (mode == 0) return blk * 128 + rr;
    int batch = blk >> 6, t0 = blk & 63;
    return batch * 8192 + t0 + ((rr >> 6) << 6) + ((rr & 63) << 7);
}

__device__ __forceinline__ void prefetch_M(uint32_t sb, int stage, int tid) {
    const char* src = (const char*)(g_Mi + (size_t)stage * 64 * DIM);
    #pragma unroll
    for (int k = 0; k < 16; k++) {
        int i  = tid + 256 * k;              // 4096 x 16B chunks
        int kc = i >> 6, e2 = i & 63;
        cpasync16(sb + SMO_M + (uint32_t)(kc * 1088 + e2 * 16), src + ((size_t)i << 4));
    }
    CPASYNC_COMMIT;
}

__global__ __launch_bounds__(THREADS)
void butterfly_kernel(const float* __restrict__ x, float* __restrict__ out,
                      int nstages, int stage_off, int mode) {
    extern __shared__ char smem[];
    const uint32_t sb = smem_u32(smem);
    float*  Xs  = (float*)(smem + SMO_X);
    float2* Msp = (float2*)(smem + SMO_M);
    float4* v4  = (float4*)(smem + SMO_V);
    float*  ssA = (float*)(smem + SMO_SS);        // [2][64]
    float*  scA = ssA + 128;                      // [2][64]

    const int tid  = threadIdx.x;
    const int lane = tid & 31;
    const int wid  = tid >> 5;
    const int blk  = blockIdx.x;
    const int mt   = wid >> 1;        // M-tile (16 a-rows)
    const int nh   = wid & 1;         // N-half (64 e's)
    const int g    = lane >> 2;       // groupID
    const int c    = lane & 3;        // threadID_in_group

    // ---- load x tile (+ v init) ----
    for (int rr = wid; rr < 128; rr += 8) {
        int gr = grow_of(mode, blk, rr);
        float4 val = ((const float4*)x)[(size_t)gr * 32 + lane];
        *(float4*)(Xs + rr * 132 + lane * 4) = val;
        if (mode == 0) v4[rr * 33 + lane] = val;       // stage-0 v = x
    }
    if (mode != 0) {
        for (int rr = wid; rr < 128; rr += 8) {
            int gr = grow_of(mode, blk, rr);
            v4[rr * 33 + lane] = ((const float4*)out)[(size_t)gr * 32 + lane];
        }
    }
    prefetch_M(sb, stage_off, tid);
    CPASYNC_WAIT0;
    __syncthreads();

    for (int ls = 0; ls < nstages; ls++) {
        // a-rows owned by this thread: i0 = mt*16+g, i1 = i0+8
        const int i0 = mt * 16 + g, i1 = i0 + 8;
        const int r0 = insert0(i0, ls), r1 = insert0(i1, ls);
        const int p0 = r0 | (1 << ls), p1 = r1 | (1 << ls);
        const float* xa0 = Xs + r0 * 132;
        const float* xa1 = Xs + r1 * 132;

        // ---- MMA: Y[a-rows][e] = X_a * M   (16 k-steps of 8) ----
        float acc[8][4];
        #pragma unroll
        for (int nt = 0; nt < 8; nt++)
            #pragma unroll
            for (int q = 0; q < 4; q++) acc[nt][q] = 0.0f;

        #pragma unroll
        for (int kk = 0; kk < 16; kk++) {
            const int d0 = kk * 8 + c;
            uint32_t A0 = __float_as_uint(xa0[d0]);
            uint32_t A1 = __float_as_uint(xa1[d0]);
            uint32_t A2 = __float_as_uint(xa0[d0 + 4]);
            uint32_t A3 = __float_as_uint(xa1[d0 + 4]);
            const float2* bp = Msp + (kk * 4 + c) * 136 + nh * 64 + g;
            #pragma unroll
            for (int nt = 0; nt < 8; nt++) {
                float2 b = bp[nt * 8];
                mma_tf32(acc[nt], A0, A1, A2, A3,
                         __float_as_uint(b.x), __float_as_uint(b.y));
            }
        }
        __syncthreads();                        // everyone done reading Msp
        if (ls + 1 < nstages) prefetch_M(sb, stage_off + ls + 1, tid);

        // ---- dots from fragments: ss = y.xa, sc = y.xb ----
        {
            float ss0 = 0.f, sc0 = 0.f, ss1 = 0.f, sc1 = 0.f;
            const float2* xa0v = (const float2*)(Xs + r0 * 132);
            const float2* xb0v = (const float2*)(Xs + p0 * 132);
            const float2* xa1v = (const float2*)(Xs + r1 * 132);
            const float2* xb1v = (const float2*)(Xs + p1 * 132);
            #pragma unroll
            for (int nt = 0; nt < 8; nt++) {
                int e2 = nh * 32 + nt * 4 + c;       // float2 index of col 2c
                float2 a0v = xa0v[e2], b0v = xb0v[e2];
                float2 a1v = xa1v[e2], b1v = xb1v[e2];
                ss0 += acc[nt][0] * a0v.x + acc[nt][1] * a0v.y;
                sc0 += acc[nt][0] * b0v.x + acc[nt][1] * b0v.y;
                ss1 += acc[nt][2] * a1v.x + acc[nt][3] * a1v.y;
                sc1 += acc[nt][2] * b1v.x + acc[nt][3] * b1v.y;
            }
            #pragma unroll
            for (int off = 1; off <= 2; off <<= 1) {
                ss0 += __shfl_xor_sync(0xffffffffu, ss0, off);
                sc0 += __shfl_xor_sync(0xffffffffu, sc0, off);
                ss1 += __shfl_xor_sync(0xffffffffu, ss1, off);
                sc1 += __shfl_xor_sync(0xffffffffu, sc1, off);
            }
            if (c == 0) {
                ssA[nh * 64 + i0] = ss0;  scA[nh * 64 + i0] = sc0;
                ssA[nh * 64 + i1] = ss1;  scA[nh * 64 + i1] = sc1;
            }
        }
        __syncthreads();                        // partials visible

        // ---- butterfly mix of v (row = tid&127, half-row = tid>>7) ----
        {
            const int vr = tid & 127, h = tid >> 7;
            const int vp = vr ^ (1 << ls);
            const int iv = compress(vr, ls);
            float ss = ssA[iv] + ssA[64 + iv];
            float sc = scA[iv] + scA[64 + iv];
            float w0 = 1.0f / (1.0f + __expf(sc - ss));   // own-row weight
            float w1 = 1.0f - w0;
            float4* vs = v4 + vr * 33 + 16 * h;
            const float4* vq = v4 + vp * 33 + 16 * h;
            float4 nv[16];
            #pragma unroll
            for (int m2 = 0; m2 < 16; m2++) {
                float4 a = vs[m2], b = vq[m2];
                nv[m2].x = w0 * a.x + w1 * b.x;
                nv[m2].y = w0 * a.y + w1 * b.y;
                nv[m2].z = w0 * a.z + w1 * b.z;
                nv[m2].w = w0 * a.w + w1 * b.w;
            }
            __syncthreads();                    // all reads before writes
            #pragma unroll
            for (int m2 = 0; m2 < 16; m2++) vs[m2] = nv[m2];
        }
        if (ls + 1 < nstages) CPASYNC_WAIT0;
        __syncthreads();
    }

    // ---- write v tile to out ----
    for (int rr = wid; rr < 128; rr += 8) {
        int gr = grow_of(mode, blk, rr);
        ((float4*)out)[(size_t)gr * 32 + lane] = v4[rr * 33 + lane];
    }
}

// ============================ launch ============================
extern "C" void kernel_launch(void* const* d_in, const int* in_sizes, int n_in,
                              void* d_out, int out_size) {
    const float* x = (const float*)d_in[0];   // (16, 8192, 128) f32
    const float* w = (const float*)d_in[1];   // (16, 2, 128, 128) f32
    float* out = (float*)d_out;

    const int smem_pre = (DIM * 129 + 16 * DIM) * 4;
    cudaFuncSetAttribute(precompute_M_kernel,
                         cudaFuncAttributeMaxDynamicSharedMemorySize, smem_pre);
    cudaFuncSetAttribute(butterfly_kernel,
                         cudaFuncAttributeMaxDynamicSharedMemorySize, SMEM_TOTAL);

    precompute_M_kernel<<<dim3(LOGN, 8), 256, smem_pre>>>(w);
    // stages 0..6 (strides 1..64): 128 contiguous rows per block
    butterfly_kernel<<<1024, THREADS, SMEM_TOTAL>>>(x, out, 7, 0, 0);
    // stages 7..12 (strides 128..4096): rows t0 + 64h + 128j per block
    butterfly_kernel<<<1024, THREADS, SMEM_TOTAL>>>(x, out, 6, 7, 1);
}

// round 4
// speedup vs baseline: 1.7936x; 1.1997x over previous
#include <cuda_runtime.h>
#include <cstdint>

#define DIM 128
#define LOGN 13
#define THREADS 256
#define SCALE 0.17677669529663688f   // 32^-0.5

// ---- dynamic smem byte offsets ----
// Xs : 128 x 132 f32 (x tile; row stride 132 words; 33-float4 stride is odd -> conflict-free f4)
// Msp: 2 buffers x 64 x 136 float2 (M pairs: [kc][e] = {M[d][e], M[d+4][e]}, d=(kc>>2)*8+(kc&3))
// SS : ssA[4][64], scA[4][64]
// W0 : per-row own-weight, 128 f32
#define SMO_X    0
#define SMO_M    67584
#define MBUF_BYTES 69632
#define SMO_SS   206848
#define SMO_W0   208896
#define SMEM_TOTAL 209408

__device__ __align__(16) float2 g_Mi[LOGN * 64 * DIM];

// ============================ helpers ============================
__device__ __forceinline__ uint32_t smem_u32(const void* p) {
    uint32_t a;
    asm("{ .reg .u64 t; cvta.to.shared.u64 t, %1; cvt.u32.u64 %0, t; }" : "=r"(a) : "l"(p));
    return a;
}
__device__ __forceinline__ void cpasync16(uint32_t dst, const void* src) {
    asm volatile("cp.async.cg.shared.global [%0], [%1], 16;" :: "r"(dst), "l"(src));
}
#define CPASYNC_COMMIT asm volatile("cp.async.commit_group;" ::: "memory")
#define CPASYNC_WAIT0  asm volatile("cp.async.wait_group 0;" ::: "memory")

__device__ __forceinline__ void mma_tf32(float* cd,
                                         uint32_t a0, uint32_t a1, uint32_t a2, uint32_t a3,
                                         uint32_t b0, uint32_t b1) {
    asm volatile("mma.sync.aligned.m16n8k8.row.col.f32.tf32.tf32.f32 "
                 "{%0,%1,%2,%3}, {%4,%5,%6,%7}, {%8,%9}, {%0,%1,%2,%3};"
                 : "+f"(cd[0]), "+f"(cd[1]), "+f"(cd[2]), "+f"(cd[3])
                 : "r"(a0), "r"(a1), "r"(a2), "r"(a3), "r"(b0), "r"(b1));
}
// insert a 0 bit at position ls (a-row index -> actual row)
__device__ __forceinline__ int insert0(int i, int ls) {
    return ((i >> ls) << (ls + 1)) | (i & ((1 << ls) - 1));
}

// ============================ precompute M (pair-interleaved) ============================
// M[d][e] = SCALE * sum_t Wq[d][t] * Wk[e][t]
__global__ void precompute_M_kernel(const float* __restrict__ w) {
    extern __shared__ float sm[];
    float* wkT  = sm;                 // [128][129] Wk transposed (padded)
    float* wq16 = sm + DIM * 129;     // 16 rows of Wq

    const int s    = blockIdx.x;
    const int dblk = blockIdx.y * 16;
    const float* Wq = w + (size_t)(2 * s) * DIM * DIM;
    const float* Wk = Wq + DIM * DIM;

    for (int i = threadIdx.x; i < DIM * DIM; i += 512) {
        int e = i >> 7, t = i & 127;
        wkT[t * 129 + e] = Wk[i];
    }
    for (int i = threadIdx.x; i < 16 * DIM; i += 512)
        wq16[i] = Wq[(size_t)dblk * DIM + i];
    __syncthreads();

    const int e  = threadIdx.x & 127;
    const int dd = threadIdx.x >> 7;          // 0..3, each handles 4 rows
    #pragma unroll
    for (int k = 0; k < 4; k++) {
        int rl = dd * 4 + k;
        float acc = 0.0f;
        #pragma unroll 8
        for (int t = 0; t < DIM; t++)
            acc += wq16[rl * DIM + t] * wkT[t * 129 + e];
        int d    = dblk + rl;
        int kc   = (d >> 3) * 4 + (d & 3);
        int comp = (d >> 2) & 1;
        ((float*)g_Mi)[(((size_t)s * 64 + kc) * DIM + e) * 2 + comp] = acc * SCALE;
    }
}

// ============================ fused butterfly ============================
// mode 0: rows = blk*128 + rr                               (stages 0..6)
// mode 1: rows = batch*8192 + t0 + 64*(rr>>6) + 128*(rr&63) (stages 7..12)
__device__ __forceinline__ int grow_of(int mode, int blk, int rr) {
    if (mode == 0) return blk * 128 + rr;
    int batch = blk >> 6, t0 = blk & 63;
    return batch * 8192 + t0 + ((rr >> 6) << 6) + ((rr & 63) << 7);
}

__device__ __forceinline__ void prefetch_M(uint32_t sb, int buf, int stage, int tid) {
    const char* src = (const char*)(g_Mi + (size_t)stage * 64 * DIM);
    const uint32_t base = sb + SMO_M + (uint32_t)buf * MBUF_BYTES;
    #pragma unroll
    for (int k = 0; k < 16; k++) {
        int i  = tid + 256 * k;              // 4096 x 16B chunks
        int kc = i >> 6, e2 = i & 63;
        cpasync16(base + (uint32_t)(kc * 1088 + e2 * 16), src + ((size_t)i << 4));
    }
    CPASYNC_COMMIT;
}

__global__ __launch_bounds__(THREADS, 1)
void butterfly_kernel(const float* __restrict__ x, float* __restrict__ out,
                      int nstages, int stage_off, int mode) {
    extern __shared__ char smem[];
    const uint32_t sb = smem_u32(smem);
    float* Xs    = (float*)(smem + SMO_X);
    float* ssA   = (float*)(smem + SMO_SS);        // [4][64]
    float* scA   = ssA + 256;                      // [4][64]
    float* w0row = (float*)(smem + SMO_W0);        // [128]

    const int tid  = threadIdx.x;
    const int lane = tid & 31;
    const int wid  = tid >> 5;
    const int blk  = blockIdx.x;
    const int mg   = wid >> 2;        // 0..1 : 32 a-rows
    const int nq   = wid & 3;         // 0..3 : 32 e-cols
    const int g    = lane >> 2;
    const int c    = lane & 3;

    // ---- x tile -> smem (coalesced) ----
    for (int rr = wid; rr < 128; rr += 8) {
        int gr = grow_of(mode, blk, rr);
        float4 val = ((const float4*)x)[(size_t)gr * 32 + lane];
        *(float4*)(Xs + rr * 132 + lane * 4) = val;
    }
    prefetch_M(sb, 0, stage_off, tid);
    __syncthreads();

    // ---- v in registers: lane owns rows lane+32j, cols float4 wid*4+k ----
    float4 v[4][4];
    if (mode == 0) {
        #pragma unroll
        for (int j = 0; j < 4; j++) {
            const float4* row = (const float4*)(Xs + (lane + 32 * j) * 132);
            #pragma unroll
            for (int k = 0; k < 4; k++) v[j][k] = row[wid * 4 + k];
        }
    } else {
        #pragma unroll
        for (int j = 0; j < 4; j++) {
            int gr = grow_of(1, blk, lane + 32 * j);
            #pragma unroll
            for (int k = 0; k < 4; k++)
                v[j][k] = ((const float4*)out)[(size_t)gr * 32 + wid * 4 + k];
        }
    }
    CPASYNC_WAIT0;
    __syncthreads();

    for (int ls = 0; ls < nstages; ls++) {
        const int cur = ls & 1;
        if (ls + 1 < nstages) prefetch_M(sb, cur ^ 1, stage_off + ls + 1, tid);

        // a-rows of this thread
        const int i0 = mg * 32 + g, i1 = i0 + 8, i2 = i0 + 16, i3 = i0 + 24;
        const int r0 = insert0(i0, ls), r1 = insert0(i1, ls);
        const int r2 = insert0(i2, ls), r3 = insert0(i3, ls);
        const float* x0 = Xs + r0 * 132;
        const float* x1 = Xs + r1 * 132;
        const float* x2 = Xs + r2 * 132;
        const float* x3 = Xs + r3 * 132;

        // ---- MMA: Y = X_a * M  (2 x m16 tiles share B) ----
        float acc[2][4][4];
        #pragma unroll
        for (int t = 0; t < 2; t++)
            #pragma unroll
            for (int nt = 0; nt < 4; nt++)
                #pragma unroll
                for (int q = 0; q < 4; q++) acc[t][nt][q] = 0.0f;

        const float2* Mb = (const float2*)(smem + SMO_M) + cur * (MBUF_BYTES / 8);
        #pragma unroll
        for (int kk = 0; kk < 16; kk++) {
            const int d0 = kk * 8 + c;
            uint32_t a00 = __float_as_uint(x0[d0]);
            uint32_t a01 = __float_as_uint(x1[d0]);
            uint32_t a02 = __float_as_uint(x0[d0 + 4]);
            uint32_t a03 = __float_as_uint(x1[d0 + 4]);
            uint32_t a10 = __float_as_uint(x2[d0]);
            uint32_t a11 = __float_as_uint(x3[d0]);
            uint32_t a12 = __float_as_uint(x2[d0 + 4]);
            uint32_t a13 = __float_as_uint(x3[d0 + 4]);
            const float2* bp = Mb + (kk * 4 + c) * 136 + nq * 32 + g;
            #pragma unroll
            for (int nt = 0; nt < 4; nt++) {
                float2 b = bp[nt * 8];
                uint32_t b0 = __float_as_uint(b.x), b1 = __float_as_uint(b.y);
                mma_tf32(acc[0][nt], a00, a01, a02, a03, b0, b1);
                mma_tf32(acc[1][nt], a10, a11, a12, a13, b0, b1);
            }
        }

        // ---- dots: ss = y.xa, sc = y.xb  (per 32-e quarter) ----
        {
            const int p0 = r0 | (1 << ls), p1 = r1 | (1 << ls);
            const int p2 = r2 | (1 << ls), p3 = r3 | (1 << ls);
            float ss0 = 0.f, ss1 = 0.f, ss2 = 0.f, ss3 = 0.f;
            float sc0 = 0.f, sc1 = 0.f, sc2 = 0.f, sc3 = 0.f;
            #pragma unroll
            for (int nt = 0; nt < 4; nt++) {
                const int e2 = nq * 16 + nt * 4 + c;      // float2 col index
                float2 A0 = ((const float2*)x0)[e2], B0 = ((const float2*)(Xs + p0 * 132))[e2];
                float2 A1 = ((const float2*)x1)[e2], B1 = ((const float2*)(Xs + p1 * 132))[e2];
                float2 A2 = ((const float2*)x2)[e2], B2 = ((const float2*)(Xs + p2 * 132))[e2];
                float2 A3 = ((const float2*)x3)[e2], B3 = ((const float2*)(Xs + p3 * 132))[e2];
                ss0 += acc[0][nt][0] * A0.x + acc[0][nt][1] * A0.y;
                sc0 += acc[0][nt][0] * B0.x + acc[0][nt][1] * B0.y;
                ss1 += acc[0][nt][2] * A1.x + acc[0][nt][3] * A1.y;
                sc1 += acc[0][nt][2] * B1.x + acc[0][nt][3] * B1.y;
                ss2 += acc[1][nt][0] * A2.x + acc[1][nt][1] * A2.y;
                sc2 += acc[1][nt][0] * B2.x + acc[1][nt][1] * B2.y;
                ss3 += acc[1][nt][2] * A3.x + acc[1][nt][3] * A3.y;
                sc3 += acc[1][nt][2] * B3.x + acc[1][nt][3] * B3.y;
            }
            #pragma unroll
            for (int off = 1; off <= 2; off <<= 1) {
                ss0 += __shfl_xor_sync(0xffffffffu, ss0, off);
                sc0 += __shfl_xor_sync(0xffffffffu, sc0, off);
                ss1 += __shfl_xor_sync(0xffffffffu, ss1, off);
                sc1 += __shfl_xor_sync(0xffffffffu, sc1, off);
                ss2 += __shfl_xor_sync(0xffffffffu, ss2, off);
                sc2 += __shfl_xor_sync(0xffffffffu, sc2, off);
                ss3 += __shfl_xor_sync(0xffffffffu, ss3, off);
                sc3 += __shfl_xor_sync(0xffffffffu, sc3, off);
            }
            if (c == 0) {
                ssA[nq * 64 + i0] = ss0;  scA[nq * 64 + i0] = sc0;
                ssA[nq * 64 + i1] = ss1;  scA[nq * 64 + i1] = sc1;
                ssA[nq * 64 + i2] = ss2;  scA[nq * 64 + i2] = sc2;
                ssA[nq * 64 + i3] = ss3;  scA[nq * 64 + i3] = sc3;
            }
        }
        __syncthreads();

        // ---- pair weights ----
        if (tid < 64) {
            const int i = tid;
            float s1 = ssA[i] + ssA[64 + i] + ssA[128 + i] + ssA[192 + i];
            float s2 = scA[i] + scA[64 + i] + scA[128 + i] + scA[192 + i];
            float w0v = 1.0f / (1.0f + __expf(s2 - s1));   // own-row weight
            int ra = insert0(i, ls);
            w0row[ra] = w0v;
            w0row[ra | (1 << ls)] = w0v;
        }
        __syncthreads();

        // ---- butterfly mix of v (registers + shfl / local swap) ----
        {
            float w0v[4], w1v[4];
            #pragma unroll
            for (int j = 0; j < 4; j++) {
                w0v[j] = w0row[lane + 32 * j];
                w1v[j] = 1.0f - w0v[j];
            }
            const int srr = 1 << ls;
            if (srr <= 16) {
                #pragma unroll
                for (int j = 0; j < 4; j++)
                    #pragma unroll
                    for (int k = 0; k < 4; k++) {
                        float4 val = v[j][k];
                        float4 pv;
                        pv.x = __shfl_xor_sync(0xffffffffu, val.x, srr);
                        pv.y = __shfl_xor_sync(0xffffffffu, val.y, srr);
                        pv.z = __shfl_xor_sync(0xffffffffu, val.z, srr);
                        pv.w = __shfl_xor_sync(0xffffffffu, val.w, srr);
                        v[j][k].x = w0v[j] * val.x + w1v[j] * pv.x;
                        v[j][k].y = w0v[j] * val.y + w1v[j] * pv.y;
                        v[j][k].z = w0v[j] * val.z + w1v[j] * pv.z;
                        v[j][k].w = w0v[j] * val.w + w1v[j] * pv.w;
                    }
            } else {
                const int dj = srr >> 5;     // 1 (stride 32) or 2 (stride 64)
                #pragma unroll
                for (int k = 0; k < 4; k++) {
                    float4 o0 = v[0][k], o1 = v[1][k], o2 = v[2][k], o3 = v[3][k];
                    const float4 ps[4] = {o0, o1, o2, o3};
                    #pragma unroll
                    for (int j = 0; j < 4; j++) {
                        float4 a = ps[j], b = ps[j ^ dj];
                        v[j][k].x = w0v[j] * a.x + w1v[j] * b.x;
                        v[j][k].y = w0v[j] * a.y + w1v[j] * b.y;
                        v[j][k].z = w0v[j] * a.z + w1v[j] * b.z;
                        v[j][k].w = w0v[j] * a.w + w1v[j] * b.w;
                    }
                }
            }
        }
        if (ls + 1 < nstages) CPASYNC_WAIT0;
        __syncthreads();
    }

    // ---- write v to out ----
    #pragma unroll
    for (int j = 0; j < 4; j++) {
        int gr = grow_of(mode, blk, lane + 32 * j);
        #pragma unroll
        for (int k = 0; k < 4; k++)
            ((float4*)out)[(size_t)gr * 32 + wid * 4 + k] = v[j][k];
    }
}

// ============================ launch ============================
extern "C" void kernel_launch(void* const* d_in, const int* in_sizes, int n_in,
                              void* d_out, int out_size) {
    const float* x = (const float*)d_in[0];   // (16, 8192, 128) f32
    const float* w = (const float*)d_in[1];   // (16, 2, 128, 128) f32
    float* out = (float*)d_out;

    const int smem_pre = (DIM * 129 + 16 * DIM) * 4;
    cudaFuncSetAttribute(precompute_M_kernel,
                         cudaFuncAttributeMaxDynamicSharedMemorySize, smem_pre);
    cudaFuncSetAttribute(butterfly_kernel,
                         cudaFuncAttributeMaxDynamicSharedMemorySize, SMEM_TOTAL);

    precompute_M_kernel<<<dim3(LOGN, 8), 512, smem_pre>>>(w);
    // stages 0..6 (strides 1..64): 128 contiguous rows per block
    butterfly_kernel<<<1024, THREADS, SMEM_TOTAL>>>(x, out, 7, 0, 0);
    // stages 7..12 (strides 128..4096): rows t0 + 64h + 128j per block
    butterfly_kernel<<<1024, THREADS, SMEM_TOTAL>>>(x, out, 6, 7, 1);
}

// round 5
// speedup vs baseline: 2.8639x; 1.5967x over previous
#include <cuda_runtime.h>
#include <cuda_fp16.h>
#include <cstdint>

#define DIM 128
#define LOGN 13
#define THREADS 256
#define SCALE 0.17677669529663688f   // 32^-0.5

// ---- dynamic smem byte offsets ----
// Xh : 128 rows x 66 half2 (fp16 x tile, padded)
// M  : 2 buffers x 32 kc-rows x 136 uint2 (packed fp16 B-fragments)
// SS : ssA[4][64], scA[4][64] f32
// W0 : per-row own-weight, 128 f32
#define SMO_XH 0
#define SMO_M  33792
#define MBUF   34816
#define SMO_SS (SMO_M + 2 * MBUF)     // 103424
#define SMO_W0 (SMO_SS + 2048)        // 105472
#define SMEM_TOTAL 105984

// packed fp16 M: [s][kc=kk*4+c][e][4 halves: k=2c,2c+1,2c+8,2c+9 of block kk]
__device__ __align__(16) __half g_Mh[LOGN * 32 * DIM * 4];

// ============================ helpers ============================
__device__ __forceinline__ uint32_t smem_u32(const void* p) {
    uint32_t a;
    asm("{ .reg .u64 t; cvta.to.shared.u64 t, %1; cvt.u32.u64 %0, t; }" : "=r"(a) : "l"(p));
    return a;
}
__device__ __forceinline__ void cpasync16(uint32_t dst, const void* src) {
    asm volatile("cp.async.cg.shared.global [%0], [%1], 16;" :: "r"(dst), "l"(src));
}
#define CPASYNC_COMMIT asm volatile("cp.async.commit_group;" ::: "memory")
#define CPASYNC_WAIT0  asm volatile("cp.async.wait_group 0;" ::: "memory")

__device__ __forceinline__ void mma_f16(float* cd,
                                        uint32_t a0, uint32_t a1, uint32_t a2, uint32_t a3,
                                        uint32_t b0, uint32_t b1) {
    asm volatile("mma.sync.aligned.m16n8k16.row.col.f32.f16.f16.f32 "
                 "{%0,%1,%2,%3}, {%4,%5,%6,%7}, {%8,%9}, {%0,%1,%2,%3};"
                 : "+f"(cd[0]), "+f"(cd[1]), "+f"(cd[2]), "+f"(cd[3])
                 : "r"(a0), "r"(a1), "r"(a2), "r"(a3), "r"(b0), "r"(b1));
}
// insert a 0 bit at position ls (a-row index -> actual row)
__device__ __forceinline__ int insert0(int i, int ls) {
    return ((i >> ls) << (ls + 1)) | (i & ((1 << ls) - 1));
}

// ============================ precompute M (fp16 B-frag layout) ============================
// M[d][e] = SCALE * sum_t Wq[d][t] * Wk[e][t]
__global__ void precompute_M_kernel(const float* __restrict__ w) {
    extern __shared__ float sm[];
    float* wkT  = sm;                 // [128][129] Wk transposed (padded)
    float* wq16 = sm + DIM * 129;     // 16 rows of Wq

    const int s    = blockIdx.x;
    const int dblk = blockIdx.y * 16;
    const float* Wq = w + (size_t)(2 * s) * DIM * DIM;
    const float* Wk = Wq + DIM * DIM;

    for (int i = threadIdx.x; i < DIM * DIM; i += 512) {
        int e = i >> 7, t = i & 127;
        wkT[t * 129 + e] = Wk[i];
    }
    for (int i = threadIdx.x; i < 16 * DIM; i += 512)
        wq16[i] = Wq[(size_t)dblk * DIM + i];
    __syncthreads();

    const int e  = threadIdx.x & 127;
    const int dd = threadIdx.x >> 7;          // 0..3, each handles 4 rows
    #pragma unroll
    for (int k = 0; k < 4; k++) {
        int rl = dd * 4 + k;
        float acc = 0.0f;
        #pragma unroll 8
        for (int t = 0; t < DIM; t++)
            acc += wq16[rl * DIM + t] * wkT[t * 129 + e];
        int d   = dblk + rl;
        int w16 = d & 15, kk = d >> 4;
        int c   = (w16 >> 1) & 3, hi = w16 >> 3, lo = w16 & 1;
        g_Mh[(((size_t)s * 32 + kk * 4 + c) * DIM + e) * 4 + hi * 2 + lo] =
            __float2half(acc * SCALE);
    }
}

// ============================ fused butterfly ============================
// mode 0: rows = blk*128 + rr                               (stages 0..6)
// mode 1: rows = batch*8192 + t0 + 64*(rr>>6) + 128*(rr&63) (stages 7..12)
__device__ __forceinline__ int grow_of(int mode, int blk, int rr) {
    if (mode == 0) return blk * 128 + rr;
    int batch = blk >> 6, t0 = blk & 63;
    return batch * 8192 + t0 + ((rr >> 6) << 6) + ((rr & 63) << 7);
}

__device__ __forceinline__ void prefetch_M(uint32_t sb, int buf, int stage, int tid) {
    const char* src = (const char*)(g_Mh + (size_t)stage * 32 * DIM * 4);
    const uint32_t base = sb + SMO_M + (uint32_t)buf * MBUF;
    #pragma unroll
    for (int k = 0; k < 8; k++) {
        int i  = tid + 256 * k;              // 2048 x 16B chunks
        int kc = i >> 6, e4 = i & 63;        // 64 chunks per kc row
        cpasync16(base + (uint32_t)(kc * 1088 + e4 * 16), src + ((size_t)i << 4));
    }
    CPASYNC_COMMIT;
}

__global__ __launch_bounds__(THREADS, 2)
void butterfly_kernel(const float* __restrict__ x, float* __restrict__ out,
                      int nstages, int stage_off, int mode) {
    extern __shared__ char smem[];
    const uint32_t sb = smem_u32(smem);
    const uint32_t* Xh32 = (const uint32_t*)(smem + SMO_XH);
    const __half2*  Xh2  = (const __half2*)(smem + SMO_XH);
    float* ssA   = (float*)(smem + SMO_SS);        // [4][64]
    float* scA   = ssA + 256;                      // [4][64]
    float* w0row = (float*)(smem + SMO_W0);        // [128]

    const int tid  = threadIdx.x;
    const int lane = tid & 31;
    const int wid  = tid >> 5;
    const int blk  = blockIdx.x;
    const int mg   = wid >> 2;        // 0..1 : 32 a-rows
    const int nq   = wid & 3;         // 0..3 : 32 e-cols
    const int g    = lane >> 2;
    const int c    = lane & 3;

    // ---- x tile -> fp16 smem (coalesced) ----
    for (int rr = wid; rr < 128; rr += 8) {
        int gr = grow_of(mode, blk, rr);
        float4 val = ((const float4*)x)[(size_t)gr * 32 + lane];
        __half2* dst = (__half2*)(smem + SMO_XH) + rr * 66 + lane * 2;
        dst[0] = __floats2half2_rn(val.x, val.y);
        dst[1] = __floats2half2_rn(val.z, val.w);
    }
    prefetch_M(sb, 0, stage_off, tid);

    // ---- v in registers straight from global ----
    float4 v[4][4];
    {
        const float4* vsrc = (mode == 0) ? (const float4*)x : (const float4*)out;
        #pragma unroll
        for (int j = 0; j < 4; j++) {
            int gr = grow_of(mode, blk, lane + 32 * j);
            #pragma unroll
            for (int k = 0; k < 4; k++)
                v[j][k] = vsrc[(size_t)gr * 32 + wid * 4 + k];
        }
    }
    CPASYNC_WAIT0;
    __syncthreads();

    for (int ls = 0; ls < nstages; ls++) {
        const int cur = ls & 1;
        if (ls + 1 < nstages) prefetch_M(sb, cur ^ 1, stage_off + ls + 1, tid);

        // a-rows of this thread
        const int i0 = mg * 32 + g, i1 = i0 + 8, i2 = i0 + 16, i3 = i0 + 24;
        const int r0 = insert0(i0, ls), r1 = insert0(i1, ls);
        const int r2 = insert0(i2, ls), r3 = insert0(i3, ls);
        const int xb0 = r0 * 66, xb1 = r1 * 66, xb2 = r2 * 66, xb3 = r3 * 66;

        // ---- MMA: Y = X_a * M  (8 k16 steps, fp16 in / fp32 acc) ----
        float acc[2][4][4];
        #pragma unroll
        for (int t = 0; t < 2; t++)
            #pragma unroll
            for (int nt = 0; nt < 4; nt++)
                #pragma unroll
                for (int q = 0; q < 4; q++) acc[t][nt][q] = 0.0f;

        const uint2* Mb = (const uint2*)(smem + SMO_M + (uint32_t)cur * MBUF);
        #pragma unroll
        for (int kk = 0; kk < 8; kk++) {
            const int ia = kk * 8 + c;
            uint32_t a00 = Xh32[xb0 + ia], a01 = Xh32[xb1 + ia];
            uint32_t a02 = Xh32[xb0 + ia + 4], a03 = Xh32[xb1 + ia + 4];
            uint32_t a10 = Xh32[xb2 + ia], a11 = Xh32[xb3 + ia];
            uint32_t a12 = Xh32[xb2 + ia + 4], a13 = Xh32[xb3 + ia + 4];
            const uint2* bp = Mb + (kk * 4 + c) * 136 + nq * 32 + g;
            #pragma unroll
            for (int nt = 0; nt < 4; nt++) {
                uint2 b = bp[nt * 8];
                mma_f16(acc[0][nt], a00, a01, a02, a03, b.x, b.y);
                mma_f16(acc[1][nt], a10, a11, a12, a13, b.x, b.y);
            }
        }

        // ---- dots: ss = y.xa, sc = y.xb  (fp16 x reads) ----
        {
            const int p0 = r0 | (1 << ls), p1 = r1 | (1 << ls);
            const int p2 = r2 | (1 << ls), p3 = r3 | (1 << ls);
            float ss0 = 0.f, ss1 = 0.f, ss2 = 0.f, ss3 = 0.f;
            float sc0 = 0.f, sc1 = 0.f, sc2 = 0.f, sc3 = 0.f;
            #pragma unroll
            for (int nt = 0; nt < 4; nt++) {
                const int e2 = nq * 16 + nt * 4 + c;      // half2 col index
                float2 A0 = __half22float2(Xh2[r0 * 66 + e2]);
                float2 B0 = __half22float2(Xh2[p0 * 66 + e2]);
                float2 A1 = __half22float2(Xh2[r1 * 66 + e2]);
                float2 B1 = __half22float2(Xh2[p1 * 66 + e2]);
                float2 A2 = __half22float2(Xh2[r2 * 66 + e2]);
                float2 B2 = __half22float2(Xh2[p2 * 66 + e2]);
                float2 A3 = __half22float2(Xh2[r3 * 66 + e2]);
                float2 B3 = __half22float2(Xh2[p3 * 66 + e2]);
                ss0 += acc[0][nt][0] * A0.x + acc[0][nt][1] * A0.y;
                sc0 += acc[0][nt][0] * B0.x + acc[0][nt][1] * B0.y;
                ss1 += acc[0][nt][2] * A1.x + acc[0][nt][3] * A1.y;
                sc1 += acc[0][nt][2] * B1.x + acc[0][nt][3] * B1.y;
                ss2 += acc[1][nt][0] * A2.x + acc[1][nt][1] * A2.y;
                sc2 += acc[1][nt][0] * B2.x + acc[1][nt][1] * B2.y;
                ss3 += acc[1][nt][2] * A3.x + acc[1][nt][3] * A3.y;
                sc3 += acc[1][nt][2] * B3.x + acc[1][nt][3] * B3.y;
            }
            #pragma unroll
            for (int off = 1; off <= 2; off <<= 1) {
                ss0 += __shfl_xor_sync(0xffffffffu, ss0, off);
                sc0 += __shfl_xor_sync(0xffffffffu, sc0, off);
                ss1 += __shfl_xor_sync(0xffffffffu, ss1, off);
                sc1 += __shfl_xor_sync(0xffffffffu, sc1, off);
                ss2 += __shfl_xor_sync(0xffffffffu, ss2, off);
                sc2 += __shfl_xor_sync(0xffffffffu, sc2, off);
                ss3 += __shfl_xor_sync(0xffffffffu, ss3, off);
                sc3 += __shfl_xor_sync(0xffffffffu, sc3, off);
            }
            if (c == 0) {
                ssA[nq * 64 + i0] = ss0;  scA[nq * 64 + i0] = sc0;
                ssA[nq * 64 + i1] = ss1;  scA[nq * 64 + i1] = sc1;
                ssA[nq * 64 + i2] = ss2;  scA[nq * 64 + i2] = sc2;
                ssA[nq * 64 + i3] = ss3;  scA[nq * 64 + i3] = sc3;
            }
        }
        __syncthreads();

        // ---- pair weights ----
        if (tid < 64) {
            const int i = tid;
            float s1 = ssA[i] + ssA[64 + i] + ssA[128 + i] + ssA[192 + i];
            float s2 = scA[i] + scA[64 + i] + scA[128 + i] + scA[192 + i];
            float w0v = 1.0f / (1.0f + __expf(s2 - s1));   // own-row weight
            int ra = insert0(i, ls);
            w0row[ra] = w0v;
            w0row[ra | (1 << ls)] = w0v;
        }
        __syncthreads();

        // ---- butterfly mix of v (registers + shfl / local swap) ----
        {
            const int srr = 1 << ls;
            if (srr <= 16) {
                #pragma unroll
                for (int j = 0; j < 4; j++) {
                    float w0v = w0row[lane + 32 * j];
                    float w1v = 1.0f - w0v;
                    #pragma unroll
                    for (int k = 0; k < 4; k++) {
                        float4 val = v[j][k];
                        float4 pv;
                        pv.x = __shfl_xor_sync(0xffffffffu, val.x, srr);
                        pv.y = __shfl_xor_sync(0xffffffffu, val.y, srr);
                        pv.z = __shfl_xor_sync(0xffffffffu, val.z, srr);
                        pv.w = __shfl_xor_sync(0xffffffffu, val.w, srr);
                        v[j][k].x = w0v * val.x + w1v * pv.x;
                        v[j][k].y = w0v * val.y + w1v * pv.y;
                        v[j][k].z = w0v * val.z + w1v * pv.z;
                        v[j][k].w = w0v * val.w + w1v * pv.w;
                    }
                }
            } else {
                const int dj = srr >> 5;     // 1 (stride 32) or 2 (stride 64)
                float w0v[4], w1v[4];
                #pragma unroll
                for (int j = 0; j < 4; j++) {
                    w0v[j] = w0row[lane + 32 * j];
                    w1v[j] = 1.0f - w0v[j];
                }
                #pragma unroll
                for (int k = 0; k < 4; k++) {
                    float4 o0 = v[0][k], o1 = v[1][k], o2 = v[2][k], o3 = v[3][k];
                    const float4 ps[4] = {o0, o1, o2, o3};
                    #pragma unroll
                    for (int j = 0; j < 4; j++) {
                        float4 a = ps[j], b = ps[j ^ dj];
                        v[j][k].x = w0v[j] * a.x + w1v[j] * b.x;
                        v[j][k].y = w0v[j] * a.y + w1v[j] * b.y;
                        v[j][k].z = w0v[j] * a.z + w1v[j] * b.z;
                        v[j][k].w = w0v[j] * a.w + w1v[j] * b.w;
                    }
                }
            }
        }
        if (ls + 1 < nstages) CPASYNC_WAIT0;
        __syncthreads();
    }

    // ---- write v to out ----
    #pragma unroll
    for (int j = 0; j < 4; j++) {
        int gr = grow_of(mode, blk, lane + 32 * j);
        #pragma unroll
        for (int k = 0; k < 4; k++)
            ((float4*)out)[(size_t)gr * 32 + wid * 4 + k] = v[j][k];
    }
}

// ============================ launch ============================
extern "C" void kernel_launch(void* const* d_in, const int* in_sizes, int n_in,
                              void* d_out, int out_size) {
    const float* x = (const float*)d_in[0];   // (16, 8192, 128) f32
    const float* w = (const float*)d_in[1];   // (16, 2, 128, 128) f32
    float* out = (float*)d_out;

    const int smem_pre = (DIM * 129 + 16 * DIM) * 4;
    cudaFuncSetAttribute(precompute_M_kernel,
                         cudaFuncAttributeMaxDynamicSharedMemorySize, smem_pre);
    cudaFuncSetAttribute(butterfly_kernel,
                         cudaFuncAttributeMaxDynamicSharedMemorySize, SMEM_TOTAL);

    precompute_M_kernel<<<dim3(LOGN, 8), 512, smem_pre>>>(w);
    // stages 0..6 (strides 1..64): 128 contiguous rows per block
    butterfly_kernel<<<1024, THREADS, SMEM_TOTAL>>>(x, out, 7, 0, 0);
    // stages 7..12 (strides 128..4096): rows t0 + 64h + 128j per block
    butterfly_kernel<<<1024, THREADS, SMEM_TOTAL>>>(x, out, 6, 7, 1);
}